// round 7
// baseline (speedup 1.0000x reference)
#include <cuda_runtime.h>
#include <cuda_fp16.h>
#include <mma.h>
#include <math.h>
#include <cstdint>

using namespace nvcuda;

#define T_TOK 2048
#define HID   2880
#define INTERN 2880
#define NE    8
#define TOPK  4
#define N1    (2*INTERN)          // 5760
#define ALPHA 1.702f
#define LIMITV 7.0f

// tiling
#define BM 256
#define BN 64
#define BK 32
#define NTHR 512
#define LDA 40                    // BK + 8 halfs pad
#define LDB 72                    // BN + 8 halfs pad
#define LDBF 72                   // epilogue float staging leading dim
#define KT (HID/BK)               // 90

// ---------------- scratch ----------------
__device__ int   d_counts[NE];
__device__ int   d_rtok[NE * T_TOK];
__device__ int   d_pos [T_TOK * TOPK];
__device__ int   d_topidx[T_TOK * TOPK];
__device__ float d_topw [T_TOK * TOPK];

__device__ __half d_xh [(size_t)T_TOK * HID];
__device__ __half d_w1h[(size_t)NE * HID * N1];
__device__ __half d_w2h[(size_t)NE * INTERN * HID];
__device__ __half d_acth[(size_t)NE * T_TOK * INTERN];
__device__ float  d_y2 [(size_t)NE * T_TOK * HID];

__device__ __forceinline__ void cpa16(void* smem, const void* gmem) {
    uint32_t s;
    asm("{ .reg .u64 t; cvta.to.shared.u64 t, %1; cvt.u32.u64 %0, t; }" : "=r"(s) : "l"(smem));
    asm volatile("cp.async.cg.shared.global [%0], [%1], 16;\n" :: "r"(s), "l"(gmem));
}
#define CP_COMMIT() asm volatile("cp.async.commit_group;\n")
#define CP_WAIT1()  asm volatile("cp.async.wait_group 1;\n")

// ---------------- fp32 -> fp16 convert (round-5 proven form) ----------------
__global__ void cvt_half_kernel(const float* __restrict__ in,
                                __half* __restrict__ out, size_t n4) {
    size_t i = (size_t)blockIdx.x * blockDim.x + threadIdx.x;
    if (i >= n4) return;
    float4 v = ((const float4*)in)[i];
    __half2 a = __floats2half2_rn(v.x, v.y);
    __half2 b = __floats2half2_rn(v.z, v.w);
    ((__half2*)out)[i * 2]     = a;
    ((__half2*)out)[i * 2 + 1] = b;
}

// ---------------- router (fp32 exact) ----------------
__global__ void router_kernel(const float* __restrict__ x,
                              const float* __restrict__ gw,
                              const float* __restrict__ gb) {
    int t = blockIdx.x;
    float acc[NE];
    #pragma unroll
    for (int e = 0; e < NE; e++) acc[e] = 0.f;
    for (int h = threadIdx.x; h < HID; h += blockDim.x) {
        float xv = x[(size_t)t * HID + h];
        const float* g = gw + (size_t)h * NE;
        #pragma unroll
        for (int e = 0; e < NE; e++) acc[e] += xv * g[e];
    }
    #pragma unroll
    for (int off = 16; off > 0; off >>= 1)
        #pragma unroll
        for (int e = 0; e < NE; e++)
            acc[e] += __shfl_down_sync(0xffffffffu, acc[e], off);
    __shared__ float sred[4][NE];
    int w = threadIdx.x >> 5, lane = threadIdx.x & 31;
    if (lane == 0)
        #pragma unroll
        for (int e = 0; e < NE; e++) sred[w][e] = acc[e];
    __syncthreads();
    if (threadIdx.x == 0) {
        float lg[NE];
        #pragma unroll
        for (int e = 0; e < NE; e++)
            lg[e] = sred[0][e] + sred[1][e] + sred[2][e] + sred[3][e] + gb[e];
        int idx[TOPK]; float val[TOPK]; bool used[NE];
        #pragma unroll
        for (int e = 0; e < NE; e++) used[e] = false;
        #pragma unroll
        for (int k = 0; k < TOPK; k++) {
            int best = -1; float bv = -INFINITY;
            #pragma unroll
            for (int e = 0; e < NE; e++)
                if (!used[e] && lg[e] > bv) { bv = lg[e]; best = e; }
            used[best] = true; idx[k] = best; val[k] = bv;
        }
        float m = val[0], ex[TOPK], s = 0.f;
        #pragma unroll
        for (int k = 0; k < TOPK; k++) { ex[k] = expf(val[k] - m); s += ex[k]; }
        float inv = 1.f / s;
        #pragma unroll
        for (int k = 0; k < TOPK; k++) {
            d_topidx[t * TOPK + k] = idx[k];
            d_topw [t * TOPK + k] = ex[k] * inv;
        }
    }
}

__global__ void reset_kernel() { if (threadIdx.x < NE) d_counts[threadIdx.x] = 0; }

__global__ void build_kernel() {
    int t = blockIdx.x * blockDim.x + threadIdx.x;
    if (t >= T_TOK) return;
    #pragma unroll
    for (int k = 0; k < TOPK; k++) {
        int e = d_topidx[t * TOPK + k];
        int p = atomicAdd(&d_counts[e], 1);
        d_rtok[e * T_TOK + p] = t;
        d_pos[t * TOPK + k] = p;
    }
}

// ---------------- GEMM1 (fp16 wmma, BM=256) fused with clamped SwiGLU -------
#define G1_STAGE (BM*LDA + 2*BK*LDB)   // 10240 + 4608 = 14848 halfs
#define G1_SMEM_B (BM * LDBF * 4)      // epilogue: 73728 B  (> 2*G1_STAGE*2 = 59392)

__global__ __launch_bounds__(NTHR) void gemm1_kernel(const float* __restrict__ b1) {
    int e  = blockIdx.z;
    int m0 = blockIdx.y * BM;
    int n0 = blockIdx.x * BN;
    int cnt = d_counts[e];
    if (m0 >= cnt) return;

    extern __shared__ __align__(16) __half sbuf[];
    __shared__ int stok[BM];

    int tid = threadIdx.x;
    if (tid < BM) {
        int r = m0 + tid;
        stok[tid] = (r < cnt) ? d_rtok[e * T_TOK + r] : d_rtok[e * T_TOK];
    }
    __syncthreads();

    const __half* Bg = d_w1h + (size_t)e * HID * N1 + n0;
    const __half* Bl = Bg + INTERN;

    auto load_stage = [&](int s, int k0) {
        __half* as = sbuf + s * G1_STAGE;
        __half* bg = as + BM * LDA;
        __half* bl = bg + BK * LDB;
        #pragma unroll
        for (int j = 0; j < 2; j++) {                 // A: 256 rows x 4 chunks
            int idx = tid + j * NTHR;
            int r = idx >> 2, c = (idx & 3) << 3;
            cpa16(as + r * LDA + c, d_xh + (size_t)stok[r] * HID + k0 + c);
        }
        {                                              // Bg (tid<256) / Bl (tid>=256)
            int h = tid & 255;
            int r = h >> 3, c = (h & 7) << 3;
            const size_t g = (size_t)(k0 + r) * N1 + c;
            if (tid < 256) cpa16(bg + r * LDB + c, Bg + g);
            else           cpa16(bl + r * LDB + c, Bl + g);
        }
        CP_COMMIT();
    };

    wmma::fragment<wmma::accumulator, 16, 16, 16, float> ag[2][2], al[2][2];
    #pragma unroll
    for (int i = 0; i < 2; i++)
        #pragma unroll
        for (int j = 0; j < 2; j++) { wmma::fill_fragment(ag[i][j], 0.f); wmma::fill_fragment(al[i][j], 0.f); }

    int wid = tid >> 5, wm = wid >> 1, wn = wid & 1;   // 16 warps: 8m x 2n, warp tile 32x32

    load_stage(0, 0);

    for (int kt = 0; kt < KT; kt++) {
        if (kt + 1 < KT) load_stage((kt + 1) & 1, (kt + 1) * BK);
        else CP_COMMIT();
        CP_WAIT1();
        __syncthreads();
        __half* as = sbuf + (kt & 1) * G1_STAGE;
        __half* bg = as + BM * LDA;
        __half* bl = bg + BK * LDB;
        #pragma unroll
        for (int kk = 0; kk < BK; kk += 16) {
            wmma::fragment<wmma::matrix_a, 16, 16, 16, __half, wmma::row_major> af[2];
            wmma::fragment<wmma::matrix_b, 16, 16, 16, __half, wmma::row_major> bfg[2], bfl[2];
            #pragma unroll
            for (int i = 0; i < 2; i++)
                wmma::load_matrix_sync(af[i], as + (wm * 32 + i * 16) * LDA + kk, LDA);
            #pragma unroll
            for (int j = 0; j < 2; j++) {
                wmma::load_matrix_sync(bfg[j], bg + kk * LDB + wn * 32 + j * 16, LDB);
                wmma::load_matrix_sync(bfl[j], bl + kk * LDB + wn * 32 + j * 16, LDB);
            }
            #pragma unroll
            for (int i = 0; i < 2; i++)
                #pragma unroll
                for (int j = 0; j < 2; j++) {
                    wmma::mma_sync(ag[i][j], af[i], bfg[j], ag[i][j]);
                    wmma::mma_sync(al[i][j], af[i], bfl[j], al[i][j]);
                }
        }
        __syncthreads();
    }

    // ---- fused epilogue: stage gate, stage lin, clamped SwiGLU, fp16 out ----
    float* stg = (float*)sbuf;   // 256*72*4 = 73728 B
    #pragma unroll
    for (int i = 0; i < 2; i++)
        #pragma unroll
        for (int j = 0; j < 2; j++)
            wmma::store_matrix_sync(stg + (size_t)(wm * 32 + i * 16) * LDBF + wn * 32 + j * 16,
                                    ag[i][j], LDBF, wmma::mem_row_major);
    __syncthreads();

    int r  = tid >> 1;            // 0..255
    int cb = (tid & 1) * 32;
    float gv[32];
    #pragma unroll
    for (int q = 0; q < 8; q++) {
        float4 v = *(const float4*)(stg + r * LDBF + cb + q * 4);
        gv[q*4+0] = v.x; gv[q*4+1] = v.y; gv[q*4+2] = v.z; gv[q*4+3] = v.w;
    }
    __syncthreads();

    #pragma unroll
    for (int i = 0; i < 2; i++)
        #pragma unroll
        for (int j = 0; j < 2; j++)
            wmma::store_matrix_sync(stg + (size_t)(wm * 32 + i * 16) * LDBF + wn * 32 + j * 16,
                                    al[i][j], LDBF, wmma::mem_row_major);
    __syncthreads();

    const float* bgp = b1 + (size_t)e * N1 + n0;
    const float* blp = bgp + INTERN;
    __half* outp = d_acth + (size_t)(e * T_TOK + m0 + r) * INTERN + n0 + cb;
    __half hb[32];
    #pragma unroll
    for (int q = 0; q < 8; q++) {
        float4 lv = *(const float4*)(stg + r * LDBF + cb + q * 4);
        float lraw[4] = {lv.x, lv.y, lv.z, lv.w};
        #pragma unroll
        for (int w = 0; w < 4; w++) {
            int c = cb + q * 4 + w;
            float g = fminf(gv[q*4+w] + bgp[c], LIMITV);
            float l = fminf(fmaxf(lraw[w] + blp[c], -LIMITV), LIMITV);
            float s = 1.0f / (1.0f + expf(-ALPHA * g));
            hb[q*4+w] = __float2half_rn(g * s * (l + 1.0f));
        }
    }
    #pragma unroll
    for (int q = 0; q < 4; q++)
        ((float4*)outp)[q] = ((float4*)hb)[q];
}

// ---------------- GEMM2 (fp16 wmma, BM=256): y2 = act @ w2[e] ---------------
#define G2_STAGE (BM*LDA + BK*LDB)     // 10240 + 2304 = 12544 halfs

__global__ __launch_bounds__(NTHR) void gemm2_kernel() {
    int e  = blockIdx.z;
    int m0 = blockIdx.y * BM;
    int n0 = blockIdx.x * BN;
    int cnt = d_counts[e];
    if (m0 >= cnt) return;

    extern __shared__ __align__(16) __half sbuf[];   // 2 * G2_STAGE

    int tid = threadIdx.x;
    const __half* Abase = d_acth + (size_t)(e * T_TOK + m0) * INTERN;
    const __half* Bbase = d_w2h + (size_t)e * INTERN * HID + n0;

    auto load_stage = [&](int s, int k0) {
        __half* as = sbuf + s * G2_STAGE;
        __half* bs = as + BM * LDA;
        #pragma unroll
        for (int j = 0; j < 2; j++) {
            int idx = tid + j * NTHR;
            int r = idx >> 2, c = (idx & 3) << 3;
            cpa16(as + r * LDA + c, Abase + (size_t)r * INTERN + k0 + c);
        }
        if (tid < 256) {
            int r = tid >> 3, c = (tid & 7) << 3;
            cpa16(bs + r * LDB + c, Bbase + (size_t)(k0 + r) * HID + c);
        }
        CP_COMMIT();
    };

    wmma::fragment<wmma::accumulator, 16, 16, 16, float> acc[2][2];
    #pragma unroll
    for (int i = 0; i < 2; i++)
        #pragma unroll
        for (int j = 0; j < 2; j++) wmma::fill_fragment(acc[i][j], 0.f);

    int wid = tid >> 5, wm = wid >> 1, wn = wid & 1;

    load_stage(0, 0);

    for (int kt = 0; kt < KT; kt++) {
        if (kt + 1 < KT) load_stage((kt + 1) & 1, (kt + 1) * BK);
        else CP_COMMIT();
        CP_WAIT1();
        __syncthreads();
        __half* as = sbuf + (kt & 1) * G2_STAGE;
        __half* bs = as + BM * LDA;
        #pragma unroll
        for (int kk = 0; kk < BK; kk += 16) {
            wmma::fragment<wmma::matrix_a, 16, 16, 16, __half, wmma::row_major> af[2];
            wmma::fragment<wmma::matrix_b, 16, 16, 16, __half, wmma::row_major> bf[2];
            #pragma unroll
            for (int i = 0; i < 2; i++)
                wmma::load_matrix_sync(af[i], as + (wm * 32 + i * 16) * LDA + kk, LDA);
            #pragma unroll
            for (int j = 0; j < 2; j++)
                wmma::load_matrix_sync(bf[j], bs + kk * LDB + wn * 32 + j * 16, LDB);
            #pragma unroll
            for (int i = 0; i < 2; i++)
                #pragma unroll
                for (int j = 0; j < 2; j++)
                    wmma::mma_sync(acc[i][j], af[i], bf[j], acc[i][j]);
        }
        __syncthreads();
    }

    float* Cbase = d_y2 + (size_t)(e * T_TOK + m0) * HID + n0;
    #pragma unroll
    for (int i = 0; i < 2; i++)
        #pragma unroll
        for (int j = 0; j < 2; j++)
            wmma::store_matrix_sync(Cbase + (size_t)(wm * 32 + i * 16) * HID + wn * 32 + j * 16,
                                    acc[i][j], HID, wmma::mem_row_major);
}

// ---------------- deterministic combine ----------------
__global__ void combine_kernel(const float* __restrict__ b2,
                               float* __restrict__ y) {
    int t = blockIdx.x;
    __shared__ int se[TOPK]; __shared__ int sp[TOPK]; __shared__ float sw[TOPK];
    if (threadIdx.x < TOPK) {
        se[threadIdx.x] = d_topidx[t * TOPK + threadIdx.x];
        sp[threadIdx.x] = d_pos  [t * TOPK + threadIdx.x];
        sw[threadIdx.x] = d_topw [t * TOPK + threadIdx.x];
    }
    __syncthreads();
    for (int n = threadIdx.x; n < HID; n += blockDim.x) {
        float s = 0.f;
        #pragma unroll
        for (int k = 0; k < TOPK; k++) {
            int e = se[k];
            size_t row = (size_t)(e * T_TOK + sp[k]);
            s += sw[k] * (d_y2[row * HID + n] + b2[(size_t)e * HID + n]);
        }
        y[(size_t)t * HID + n] = s;
    }
}

// ---------------- launch ----------------
extern "C" void kernel_launch(void* const* d_in, const int* in_sizes, int n_in,
                              void* d_out, int out_size) {
    const float* x  = (const float*)d_in[0];
    const float* gw = (const float*)d_in[1];
    const float* gb = (const float*)d_in[2];
    const float* w1 = (const float*)d_in[3];
    const float* b1 = (const float*)d_in[4];
    const float* w2 = (const float*)d_in[5];
    const float* b2 = (const float*)d_in[6];
    float* y = (float*)d_out;

    static int smem_set = 0;
    if (!smem_set) {
        cudaFuncSetAttribute(gemm1_kernel, cudaFuncAttributeMaxDynamicSharedMemorySize, G1_SMEM_B);
        cudaFuncSetAttribute(gemm2_kernel, cudaFuncAttributeMaxDynamicSharedMemorySize,
                             2 * G2_STAGE * (int)sizeof(__half));
        smem_set = 1;
    }

    reset_kernel<<<1, 32>>>();
    router_kernel<<<T_TOK, 128>>>(x, gw, gb);
    build_kernel<<<(T_TOK + 255) / 256, 256>>>();

    // fp32 -> fp16 pre-pass (round-5 proven form)
    {
        __half* p;
        size_t n4;
        cudaGetSymbolAddress((void**)&p, d_xh);
        n4 = (size_t)T_TOK * HID / 4;
        cvt_half_kernel<<<(unsigned)((n4 + 255) / 256), 256>>>(x, p, n4);
        cudaGetSymbolAddress((void**)&p, d_w1h);
        n4 = (size_t)NE * HID * N1 / 4;
        cvt_half_kernel<<<(unsigned)((n4 + 255) / 256), 256>>>(w1, p, n4);
        cudaGetSymbolAddress((void**)&p, d_w2h);
        n4 = (size_t)NE * INTERN * HID / 4;
        cvt_half_kernel<<<(unsigned)((n4 + 255) / 256), 256>>>(w2, p, n4);
    }

    dim3 g1(INTERN / BN, T_TOK / BM, NE);   // (45, 8, 8)
    gemm1_kernel<<<g1, NTHR, G1_SMEM_B>>>(b1);

    dim3 g2(HID / BN, T_TOK / BM, NE);      // (45, 8, 8)
    gemm2_kernel<<<g2, NTHR, 2 * G2_STAGE * sizeof(__half)>>>();

    combine_kernel<<<T_TOK, 256>>>(b2, y);
}

// round 8
// speedup vs baseline: 1.3092x; 1.3092x over previous
#include <cuda_runtime.h>
#include <cuda_fp16.h>
#include <mma.h>
#include <math.h>
#include <cstdint>

using namespace nvcuda;

#define T_TOK 2048
#define HID   2880
#define INTERN 2880
#define NE    8
#define TOPK  4
#define N1    (2*INTERN)          // 5760
#define ALPHA 1.702f
#define LIMITV 7.0f

// tiling (round-5 proven config)
#define BM 128
#define BN 64
#define BK 32
#define LDA 40                    // BK + 8 halfs pad
#define LDB 72                    // BN + 8 halfs pad
#define LDBF 72                   // epilogue float staging leading dim
#define KT (HID/BK)               // 90

// ---------------- scratch ----------------
__device__ int   d_counts[NE];
__device__ int   d_rtok[NE * T_TOK];
__device__ int   d_pos [T_TOK * TOPK];
__device__ int   d_topidx[T_TOK * TOPK];
__device__ float d_topw [T_TOK * TOPK];

__device__ __half d_xh [(size_t)T_TOK * HID];
__device__ __half d_w1h[(size_t)NE * HID * N1];
__device__ __half d_w2h[(size_t)NE * INTERN * HID];
__device__ __half d_acth[(size_t)NE * T_TOK * INTERN];
__device__ float  d_y2 [(size_t)NE * T_TOK * HID];

__device__ __forceinline__ void cpa16(void* smem, const void* gmem) {
    uint32_t s;
    asm("{ .reg .u64 t; cvta.to.shared.u64 t, %1; cvt.u32.u64 %0, t; }" : "=r"(s) : "l"(smem));
    asm volatile("cp.async.cg.shared.global [%0], [%1], 16;\n" :: "r"(s), "l"(gmem));
}
#define CP_COMMIT() asm volatile("cp.async.commit_group;\n")
#define CP_WAIT1()  asm volatile("cp.async.wait_group 1;\n")

// ---------------- fp32 -> fp16 convert: grid-stride MLP4, 8B packed stores ---
__global__ void cvt_half_kernel(const float* __restrict__ in,
                                __half* __restrict__ out, size_t n4) {
    size_t S = (size_t)gridDim.x * blockDim.x;
    size_t i = (size_t)blockIdx.x * blockDim.x + threadIdx.x;
    #pragma unroll
    for (int u = 0; u < 4; u++) {
        if (i < n4) {
            float4 v = ((const float4*)in)[i];
            union { __half2 h[2]; uint2 u2; } pk;
            pk.h[0] = __floats2half2_rn(v.x, v.y);
            pk.h[1] = __floats2half2_rn(v.z, v.w);
            ((uint2*)out)[i] = pk.u2;
        }
        i += S;
    }
}

// ---------------- router (fp32 exact) ----------------
__global__ void router_kernel(const float* __restrict__ x,
                              const float* __restrict__ gw,
                              const float* __restrict__ gb) {
    int t = blockIdx.x;
    float acc[NE];
    #pragma unroll
    for (int e = 0; e < NE; e++) acc[e] = 0.f;
    for (int h = threadIdx.x; h < HID; h += blockDim.x) {
        float xv = x[(size_t)t * HID + h];
        const float* g = gw + (size_t)h * NE;
        #pragma unroll
        for (int e = 0; e < NE; e++) acc[e] += xv * g[e];
    }
    #pragma unroll
    for (int off = 16; off > 0; off >>= 1)
        #pragma unroll
        for (int e = 0; e < NE; e++)
            acc[e] += __shfl_down_sync(0xffffffffu, acc[e], off);
    __shared__ float sred[4][NE];
    int w = threadIdx.x >> 5, lane = threadIdx.x & 31;
    if (lane == 0)
        #pragma unroll
        for (int e = 0; e < NE; e++) sred[w][e] = acc[e];
    __syncthreads();
    if (threadIdx.x == 0) {
        float lg[NE];
        #pragma unroll
        for (int e = 0; e < NE; e++)
            lg[e] = sred[0][e] + sred[1][e] + sred[2][e] + sred[3][e] + gb[e];
        int idx[TOPK]; float val[TOPK]; bool used[NE];
        #pragma unroll
        for (int e = 0; e < NE; e++) used[e] = false;
        #pragma unroll
        for (int k = 0; k < TOPK; k++) {
            int best = -1; float bv = -INFINITY;
            #pragma unroll
            for (int e = 0; e < NE; e++)
                if (!used[e] && lg[e] > bv) { bv = lg[e]; best = e; }
            used[best] = true; idx[k] = best; val[k] = bv;
        }
        float m = val[0], ex[TOPK], s = 0.f;
        #pragma unroll
        for (int k = 0; k < TOPK; k++) { ex[k] = expf(val[k] - m); s += ex[k]; }
        float inv = 1.f / s;
        #pragma unroll
        for (int k = 0; k < TOPK; k++) {
            d_topidx[t * TOPK + k] = idx[k];
            d_topw [t * TOPK + k] = ex[k] * inv;
        }
    }
}

__global__ void reset_kernel() { if (threadIdx.x < NE) d_counts[threadIdx.x] = 0; }

__global__ void build_kernel() {
    int t = blockIdx.x * blockDim.x + threadIdx.x;
    if (t >= T_TOK) return;
    #pragma unroll
    for (int k = 0; k < TOPK; k++) {
        int e = d_topidx[t * TOPK + k];
        int p = atomicAdd(&d_counts[e], 1);
        d_rtok[e * T_TOK + p] = t;
        d_pos[t * TOPK + k] = p;
    }
}

// ---------------- GEMM1 (fp16 wmma) fused with clamped SwiGLU ----------------
// grid = (m-tiles, n-tiles, experts): m fastest -> co-resident CTAs share B panels in L2
#define G1_STAGE (BM*LDA + 2*BK*LDB)   // 5120 + 4608 halfs = 9728

__global__ __launch_bounds__(256) void gemm1_kernel(const float* __restrict__ b1) {
    int e  = blockIdx.z;
    int m0 = blockIdx.x * BM;
    int n0 = blockIdx.y * BN;
    int cnt = d_counts[e];
    if (m0 >= cnt) return;

    __shared__ __align__(16) __half sbuf[2 * G1_STAGE];   // 38912 B
    __shared__ int stok[BM];

    int tid = threadIdx.x;
    if (tid < BM) {
        int r = m0 + tid;
        stok[tid] = (r < cnt) ? d_rtok[e * T_TOK + r] : d_rtok[e * T_TOK];
    }
    __syncthreads();

    const __half* Bg = d_w1h + (size_t)e * HID * N1 + n0;
    const __half* Bl = Bg + INTERN;

    auto load_stage = [&](int s, int k0) {
        __half* as = sbuf + s * G1_STAGE;
        __half* bg = as + BM * LDA;
        __half* bl = bg + BK * LDB;
        #pragma unroll
        for (int j = 0; j < 2; j++) {                 // A: 128 rows x 4 chunks
            int idx = tid + j * 256;
            int r = idx >> 2, c = (idx & 3) << 3;
            cpa16(as + r * LDA + c, d_xh + (size_t)stok[r] * HID + k0 + c);
        }
        {                                              // Bg, Bl: 32 rows x 8 chunks
            int r = tid >> 3, c = (tid & 7) << 3;
            const size_t g = (size_t)(k0 + r) * N1 + c;
            cpa16(bg + r * LDB + c, Bg + g);
            cpa16(bl + r * LDB + c, Bl + g);
        }
        CP_COMMIT();
    };

    wmma::fragment<wmma::accumulator, 16, 16, 16, float> ag[2][2], al[2][2];
    #pragma unroll
    for (int i = 0; i < 2; i++)
        #pragma unroll
        for (int j = 0; j < 2; j++) { wmma::fill_fragment(ag[i][j], 0.f); wmma::fill_fragment(al[i][j], 0.f); }

    int wid = tid >> 5, wm = wid >> 1, wn = wid & 1;   // 8 warps: 4m x 2n

    load_stage(0, 0);

    for (int kt = 0; kt < KT; kt++) {
        if (kt + 1 < KT) load_stage((kt + 1) & 1, (kt + 1) * BK);
        else CP_COMMIT();
        CP_WAIT1();
        __syncthreads();
        __half* as = sbuf + (kt & 1) * G1_STAGE;
        __half* bg = as + BM * LDA;
        __half* bl = bg + BK * LDB;
        #pragma unroll
        for (int kk = 0; kk < BK; kk += 16) {
            wmma::fragment<wmma::matrix_a, 16, 16, 16, __half, wmma::row_major> af[2];
            wmma::fragment<wmma::matrix_b, 16, 16, 16, __half, wmma::row_major> bfg[2], bfl[2];
            #pragma unroll
            for (int i = 0; i < 2; i++)
                wmma::load_matrix_sync(af[i], as + (wm * 32 + i * 16) * LDA + kk, LDA);
            #pragma unroll
            for (int j = 0; j < 2; j++) {
                wmma::load_matrix_sync(bfg[j], bg + kk * LDB + wn * 32 + j * 16, LDB);
                wmma::load_matrix_sync(bfl[j], bl + kk * LDB + wn * 32 + j * 16, LDB);
            }
            #pragma unroll
            for (int i = 0; i < 2; i++)
                #pragma unroll
                for (int j = 0; j < 2; j++) {
                    wmma::mma_sync(ag[i][j], af[i], bfg[j], ag[i][j]);
                    wmma::mma_sync(al[i][j], af[i], bfl[j], al[i][j]);
                }
        }
        __syncthreads();
    }

    // ---- fused epilogue: stage gate, stage lin, clamped SwiGLU, fp16 out ----
    float* stg = (float*)sbuf;   // 128*72*4 = 36864 B <= 38912 B
    #pragma unroll
    for (int i = 0; i < 2; i++)
        #pragma unroll
        for (int j = 0; j < 2; j++)
            wmma::store_matrix_sync(stg + (size_t)(wm * 32 + i * 16) * LDBF + wn * 32 + j * 16,
                                    ag[i][j], LDBF, wmma::mem_row_major);
    __syncthreads();

    int r  = tid >> 1;
    int cb = (tid & 1) * 32;
    float gv[32];
    #pragma unroll
    for (int q = 0; q < 8; q++) {
        float4 v = *(const float4*)(stg + r * LDBF + cb + q * 4);
        gv[q*4+0] = v.x; gv[q*4+1] = v.y; gv[q*4+2] = v.z; gv[q*4+3] = v.w;
    }
    __syncthreads();

    #pragma unroll
    for (int i = 0; i < 2; i++)
        #pragma unroll
        for (int j = 0; j < 2; j++)
            wmma::store_matrix_sync(stg + (size_t)(wm * 32 + i * 16) * LDBF + wn * 32 + j * 16,
                                    al[i][j], LDBF, wmma::mem_row_major);
    __syncthreads();

    const float* bgp = b1 + (size_t)e * N1 + n0;
    const float* blp = bgp + INTERN;
    __half* outp = d_acth + (size_t)(e * T_TOK + m0 + r) * INTERN + n0 + cb;
    __half hb[32];
    #pragma unroll
    for (int q = 0; q < 8; q++) {
        float4 lv = *(const float4*)(stg + r * LDBF + cb + q * 4);
        float lraw[4] = {lv.x, lv.y, lv.z, lv.w};
        #pragma unroll
        for (int w = 0; w < 4; w++) {
            int c = cb + q * 4 + w;
            float g = fminf(gv[q*4+w] + bgp[c], LIMITV);
            float l = fminf(fmaxf(lraw[w] + blp[c], -LIMITV), LIMITV);
            float s = 1.0f / (1.0f + expf(-ALPHA * g));
            hb[q*4+w] = __float2half_rn(g * s * (l + 1.0f));
        }
    }
    #pragma unroll
    for (int q = 0; q < 4; q++)
        ((float4*)outp)[q] = ((float4*)hb)[q];
}

// ---------------- GEMM2 (fp16 wmma): y2 = act @ w2[e] ----------------
#define G2_STAGE (BM*LDA + BK*LDB)     // 5120 + 2304 = 7424 halfs

__global__ __launch_bounds__(256) void gemm2_kernel() {
    int e  = blockIdx.z;
    int m0 = blockIdx.x * BM;
    int n0 = blockIdx.y * BN;
    int cnt = d_counts[e];
    if (m0 >= cnt) return;

    __shared__ __align__(16) __half sbuf[2 * G2_STAGE];   // 29696 B

    int tid = threadIdx.x;
    const __half* Abase = d_acth + (size_t)(e * T_TOK + m0) * INTERN;
    const __half* Bbase = d_w2h + (size_t)e * INTERN * HID + n0;

    auto load_stage = [&](int s, int k0) {
        __half* as = sbuf + s * G2_STAGE;
        __half* bs = as + BM * LDA;
        #pragma unroll
        for (int j = 0; j < 2; j++) {
            int idx = tid + j * 256;
            int r = idx >> 2, c = (idx & 3) << 3;
            cpa16(as + r * LDA + c, Abase + (size_t)r * INTERN + k0 + c);
        }
        {
            int r = tid >> 3, c = (tid & 7) << 3;
            cpa16(bs + r * LDB + c, Bbase + (size_t)(k0 + r) * HID + c);
        }
        CP_COMMIT();
    };

    wmma::fragment<wmma::accumulator, 16, 16, 16, float> acc[2][2];
    #pragma unroll
    for (int i = 0; i < 2; i++)
        #pragma unroll
        for (int j = 0; j < 2; j++) wmma::fill_fragment(acc[i][j], 0.f);

    int wid = tid >> 5, wm = wid >> 1, wn = wid & 1;

    load_stage(0, 0);

    for (int kt = 0; kt < KT; kt++) {
        if (kt + 1 < KT) load_stage((kt + 1) & 1, (kt + 1) * BK);
        else CP_COMMIT();
        CP_WAIT1();
        __syncthreads();
        __half* as = sbuf + (kt & 1) * G2_STAGE;
        __half* bs = as + BM * LDA;
        #pragma unroll
        for (int kk = 0; kk < BK; kk += 16) {
            wmma::fragment<wmma::matrix_a, 16, 16, 16, __half, wmma::row_major> af[2];
            wmma::fragment<wmma::matrix_b, 16, 16, 16, __half, wmma::row_major> bf[2];
            #pragma unroll
            for (int i = 0; i < 2; i++)
                wmma::load_matrix_sync(af[i], as + (wm * 32 + i * 16) * LDA + kk, LDA);
            #pragma unroll
            for (int j = 0; j < 2; j++)
                wmma::load_matrix_sync(bf[j], bs + kk * LDB + wn * 32 + j * 16, LDB);
            #pragma unroll
            for (int i = 0; i < 2; i++)
                #pragma unroll
                for (int j = 0; j < 2; j++)
                    wmma::mma_sync(acc[i][j], af[i], bf[j], acc[i][j]);
        }
        __syncthreads();
    }

    float* Cbase = d_y2 + (size_t)(e * T_TOK + m0) * HID + n0;
    #pragma unroll
    for (int i = 0; i < 2; i++)
        #pragma unroll
        for (int j = 0; j < 2; j++)
            wmma::store_matrix_sync(Cbase + (size_t)(wm * 32 + i * 16) * HID + wn * 32 + j * 16,
                                    acc[i][j], HID, wmma::mem_row_major);
}

// ---------------- deterministic combine ----------------
__global__ void combine_kernel(const float* __restrict__ b2,
                               float* __restrict__ y) {
    int t = blockIdx.x;
    __shared__ int se[TOPK]; __shared__ int sp[TOPK]; __shared__ float sw[TOPK];
    if (threadIdx.x < TOPK) {
        se[threadIdx.x] = d_topidx[t * TOPK + threadIdx.x];
        sp[threadIdx.x] = d_pos  [t * TOPK + threadIdx.x];
        sw[threadIdx.x] = d_topw [t * TOPK + threadIdx.x];
    }
    __syncthreads();
    for (int n = threadIdx.x; n < HID; n += blockDim.x) {
        float s = 0.f;
        #pragma unroll
        for (int k = 0; k < TOPK; k++) {
            int e = se[k];
            size_t row = (size_t)(e * T_TOK + sp[k]);
            s += sw[k] * (d_y2[row * HID + n] + b2[(size_t)e * HID + n]);
        }
        y[(size_t)t * HID + n] = s;
    }
}

// ---------------- launch ----------------
extern "C" void kernel_launch(void* const* d_in, const int* in_sizes, int n_in,
                              void* d_out, int out_size) {
    const float* x  = (const float*)d_in[0];
    const float* gw = (const float*)d_in[1];
    const float* gb = (const float*)d_in[2];
    const float* w1 = (const float*)d_in[3];
    const float* b1 = (const float*)d_in[4];
    const float* w2 = (const float*)d_in[5];
    const float* b2 = (const float*)d_in[6];
    float* y = (float*)d_out;

    reset_kernel<<<1, 32>>>();
    router_kernel<<<T_TOK, 128>>>(x, gw, gb);
    build_kernel<<<(T_TOK + 255) / 256, 256>>>();

    // fp32 -> fp16 pre-pass (grid-stride, coalesced)
    {
        __half* p;
        size_t n4;
        cudaGetSymbolAddress((void**)&p, d_xh);
        n4 = (size_t)T_TOK * HID / 4;
        cvt_half_kernel<<<(unsigned)((n4 + 1023) / 1024), 256>>>(x, p, n4);
        cudaGetSymbolAddress((void**)&p, d_w1h);
        n4 = (size_t)NE * HID * N1 / 4;
        cvt_half_kernel<<<(unsigned)((n4 + 1023) / 1024), 256>>>(w1, p, n4);
        cudaGetSymbolAddress((void**)&p, d_w2h);
        n4 = (size_t)NE * INTERN * HID / 4;
        cvt_half_kernel<<<(unsigned)((n4 + 1023) / 1024), 256>>>(w2, p, n4);
    }

    // m-tiles fastest: co-resident CTAs share B panels (L2 reuse)
    dim3 g1(T_TOK / BM, INTERN / BN, NE);   // (16, 45, 8)
    gemm1_kernel<<<g1, 256>>>(b1);

    dim3 g2(T_TOK / BM, HID / BN, NE);      // (16, 45, 8)
    gemm2_kernel<<<g2, 256>>>();

    combine_kernel<<<T_TOK, 256>>>(b2, y);
}

// round 10
// speedup vs baseline: 1.3308x; 1.0165x over previous
#include <cuda_runtime.h>
#include <cuda_fp16.h>
#include <mma.h>
#include <math.h>
#include <cstdint>

using namespace nvcuda;

#define T_TOK 2048
#define HID   2880
#define INTERN 2880
#define NE    8
#define TOPK  4
#define N1    (2*INTERN)          // 5760
#define ALPHA 1.702f
#define LIMITV 7.0f

// tiling
#define BM 128
#define BN 64
#define BK 32
#define LDA 40                    // BK + 8 halfs pad
#define LDB 72                    // BN + 8 halfs pad
#define LDBF 72                   // epilogue float staging leading dim
#define KT (HID/BK)               // 90
#define NSTG 3

// ---------------- scratch ----------------
__device__ int   d_counts[NE];
__device__ int   d_rtok[NE * T_TOK];
__device__ int   d_pos [T_TOK * TOPK];
__device__ int   d_topidx[T_TOK * TOPK];
__device__ float d_topw [T_TOK * TOPK];

__device__ __half d_xh [(size_t)T_TOK * HID];
__device__ __half d_w1h[(size_t)NE * HID * N1];
__device__ __half d_w2h[(size_t)NE * INTERN * HID];
__device__ __half d_acth[(size_t)NE * T_TOK * INTERN];
__device__ float  d_y2 [(size_t)NE * T_TOK * HID];

__device__ __forceinline__ void cpa16(void* smem, const void* gmem) {
    uint32_t s;
    asm("{ .reg .u64 t; cvta.to.shared.u64 t, %1; cvt.u32.u64 %0, t; }" : "=r"(s) : "l"(smem));
    asm volatile("cp.async.cg.shared.global [%0], [%1], 16;\n" :: "r"(s), "l"(gmem));
}
#define CP_COMMIT() asm volatile("cp.async.commit_group;\n")
#define CP_WAITG1() asm volatile("cp.async.wait_group 1;\n")

// ---------------- fp32 -> fp16 convert: 32B loads, 16B stores per thread ----
__global__ void cvt_half_kernel(const float* __restrict__ in,
                                __half* __restrict__ out, size_t n8) {
    size_t i = (size_t)blockIdx.x * blockDim.x + threadIdx.x;   // unit: 8 floats
    if (i >= n8) return;
    float4 a = ((const float4*)in)[2 * i];
    float4 b = ((const float4*)in)[2 * i + 1];
    union { __half2 h[4]; uint4 u4; } pk;
    pk.h[0] = __floats2half2_rn(a.x, a.y);
    pk.h[1] = __floats2half2_rn(a.z, a.w);
    pk.h[2] = __floats2half2_rn(b.x, b.y);
    pk.h[3] = __floats2half2_rn(b.z, b.w);
    ((uint4*)out)[i] = pk.u4;
}

// ---------------- router (fp32 exact) ----------------
__global__ void router_kernel(const float* __restrict__ x,
                              const float* __restrict__ gw,
                              const float* __restrict__ gb) {
    int t = blockIdx.x;
    float acc[NE];
    #pragma unroll
    for (int e = 0; e < NE; e++) acc[e] = 0.f;
    for (int h = threadIdx.x; h < HID; h += blockDim.x) {
        float xv = x[(size_t)t * HID + h];
        const float* g = gw + (size_t)h * NE;
        #pragma unroll
        for (int e = 0; e < NE; e++) acc[e] += xv * g[e];
    }
    #pragma unroll
    for (int off = 16; off > 0; off >>= 1)
        #pragma unroll
        for (int e = 0; e < NE; e++)
            acc[e] += __shfl_down_sync(0xffffffffu, acc[e], off);
    __shared__ float sred[4][NE];
    int w = threadIdx.x >> 5, lane = threadIdx.x & 31;
    if (lane == 0)
        #pragma unroll
        for (int e = 0; e < NE; e++) sred[w][e] = acc[e];
    __syncthreads();
    if (threadIdx.x == 0) {
        float lg[NE];
        #pragma unroll
        for (int e = 0; e < NE; e++)
            lg[e] = sred[0][e] + sred[1][e] + sred[2][e] + sred[3][e] + gb[e];
        int idx[TOPK]; float val[TOPK]; bool used[NE];
        #pragma unroll
        for (int e = 0; e < NE; e++) used[e] = false;
        #pragma unroll
        for (int k = 0; k < TOPK; k++) {
            int best = -1; float bv = -INFINITY;
            #pragma unroll
            for (int e = 0; e < NE; e++)
                if (!used[e] && lg[e] > bv) { bv = lg[e]; best = e; }
            used[best] = true; idx[k] = best; val[k] = bv;
        }
        float m = val[0], ex[TOPK], s = 0.f;
        #pragma unroll
        for (int k = 0; k < TOPK; k++) { ex[k] = expf(val[k] - m); s += ex[k]; }
        float inv = 1.f / s;
        #pragma unroll
        for (int k = 0; k < TOPK; k++) {
            d_topidx[t * TOPK + k] = idx[k];
            d_topw [t * TOPK + k] = ex[k] * inv;
        }
    }
}

__global__ void reset_kernel() { if (threadIdx.x < NE) d_counts[threadIdx.x] = 0; }

__global__ void build_kernel() {
    int t = blockIdx.x * blockDim.x + threadIdx.x;
    if (t >= T_TOK) return;
    #pragma unroll
    for (int k = 0; k < TOPK; k++) {
        int e = d_topidx[t * TOPK + k];
        int p = atomicAdd(&d_counts[e], 1);
        d_rtok[e * T_TOK + p] = t;
        d_pos[t * TOPK + k] = p;
    }
}

// ---------------- GEMM1 (fp16 wmma, 3-stage pipe) fused with clamped SwiGLU --
#define G1_STAGE (BM*LDA + 2*BK*LDB)   // 9728 halfs
#define G1_SMEM  (NSTG * G1_STAGE * 2) // 58368 B

__global__ __launch_bounds__(256) void gemm1_kernel(const float* __restrict__ b1) {
    int e  = blockIdx.z;
    int m0 = blockIdx.x * BM;
    int n0 = blockIdx.y * BN;
    int cnt = d_counts[e];
    if (m0 >= cnt) return;

    extern __shared__ __align__(16) __half sbuf[];
    __shared__ int stok[BM];

    int tid = threadIdx.x;
    if (tid < BM) {
        int r = m0 + tid;
        stok[tid] = (r < cnt) ? d_rtok[e * T_TOK + r] : d_rtok[e * T_TOK];
    }
    __syncthreads();

    const __half* Bg = d_w1h + (size_t)e * HID * N1 + n0;
    const __half* Bl = Bg + INTERN;

    auto load_stage = [&](int s, int k0) {
        __half* as = sbuf + s * G1_STAGE;
        __half* bg = as + BM * LDA;
        __half* bl = bg + BK * LDB;
        #pragma unroll
        for (int j = 0; j < 2; j++) {                 // A: 128 rows x 4 chunks
            int idx = tid + j * 256;
            int r = idx >> 2, c = (idx & 3) << 3;
            cpa16(as + r * LDA + c, d_xh + (size_t)stok[r] * HID + k0 + c);
        }
        {                                              // Bg, Bl: 32 rows x 8 chunks
            int r = tid >> 3, c = (tid & 7) << 3;
            const size_t g = (size_t)(k0 + r) * N1 + c;
            cpa16(bg + r * LDB + c, Bg + g);
            cpa16(bl + r * LDB + c, Bl + g);
        }
        CP_COMMIT();
    };

    wmma::fragment<wmma::accumulator, 16, 16, 16, float> ag[2][2], al[2][2];
    #pragma unroll
    for (int i = 0; i < 2; i++)
        #pragma unroll
        for (int j = 0; j < 2; j++) { wmma::fill_fragment(ag[i][j], 0.f); wmma::fill_fragment(al[i][j], 0.f); }

    int wid = tid >> 5, wm = wid >> 1, wn = wid & 1;   // 8 warps: 4m x 2n

    load_stage(0, 0);
    load_stage(1, BK);

    int sc = 0;          // slot of tile kt
    int sl = 2;          // slot for tile kt+2
    for (int kt = 0; kt < KT; kt++) {
        CP_WAITG1();                     // tile kt resident (empty groups keep ledger aligned)
        __syncthreads();                 // RAW for slot sc; WAR: all threads past compute(kt-1)
        if (kt + 2 < KT) load_stage(sl, (kt + 2) * BK);
        else CP_COMMIT();                // empty group: keeps wait_group 1 == "tile kt done"

        __half* as = sbuf + sc * G1_STAGE;
        __half* bg = as + BM * LDA;
        __half* bl = bg + BK * LDB;
        #pragma unroll
        for (int kk = 0; kk < BK; kk += 16) {
            wmma::fragment<wmma::matrix_a, 16, 16, 16, __half, wmma::row_major> af[2];
            wmma::fragment<wmma::matrix_b, 16, 16, 16, __half, wmma::row_major> bfg[2], bfl[2];
            #pragma unroll
            for (int i = 0; i < 2; i++)
                wmma::load_matrix_sync(af[i], as + (wm * 32 + i * 16) * LDA + kk, LDA);
            #pragma unroll
            for (int j = 0; j < 2; j++) {
                wmma::load_matrix_sync(bfg[j], bg + kk * LDB + wn * 32 + j * 16, LDB);
                wmma::load_matrix_sync(bfl[j], bl + kk * LDB + wn * 32 + j * 16, LDB);
            }
            #pragma unroll
            for (int i = 0; i < 2; i++)
                #pragma unroll
                for (int j = 0; j < 2; j++) {
                    wmma::mma_sync(ag[i][j], af[i], bfg[j], ag[i][j]);
                    wmma::mma_sync(al[i][j], af[i], bfl[j], al[i][j]);
                }
        }
        sc = (sc == NSTG - 1) ? 0 : sc + 1;
        sl = (sl == NSTG - 1) ? 0 : sl + 1;
    }
    __syncthreads();   // all compute done before smem reuse in epilogue

    // ---- fused epilogue: stage gate, stage lin, clamped SwiGLU, fp16 out ----
    float* stg = (float*)sbuf;   // 128*72*4 = 36864 B <= G1_SMEM
    #pragma unroll
    for (int i = 0; i < 2; i++)
        #pragma unroll
        for (int j = 0; j < 2; j++)
            wmma::store_matrix_sync(stg + (size_t)(wm * 32 + i * 16) * LDBF + wn * 32 + j * 16,
                                    ag[i][j], LDBF, wmma::mem_row_major);
    __syncthreads();

    int r  = tid >> 1;
    int cb = (tid & 1) * 32;
    float gv[32];
    #pragma unroll
    for (int q = 0; q < 8; q++) {
        float4 v = *(const float4*)(stg + r * LDBF + cb + q * 4);
        gv[q*4+0] = v.x; gv[q*4+1] = v.y; gv[q*4+2] = v.z; gv[q*4+3] = v.w;
    }
    __syncthreads();

    #pragma unroll
    for (int i = 0; i < 2; i++)
        #pragma unroll
        for (int j = 0; j < 2; j++)
            wmma::store_matrix_sync(stg + (size_t)(wm * 32 + i * 16) * LDBF + wn * 32 + j * 16,
                                    al[i][j], LDBF, wmma::mem_row_major);
    __syncthreads();

    const float* bgp = b1 + (size_t)e * N1 + n0;
    const float* blp = bgp + INTERN;
    __half* outp = d_acth + (size_t)(e * T_TOK + m0 + r) * INTERN + n0 + cb;
    __half hb[32];
    #pragma unroll
    for (int q = 0; q < 8; q++) {
        float4 lv = *(const float4*)(stg + r * LDBF + cb + q * 4);
        float lraw[4] = {lv.x, lv.y, lv.z, lv.w};
        #pragma unroll
        for (int w = 0; w < 4; w++) {
            int c = cb + q * 4 + w;
            float g = fminf(gv[q*4+w] + bgp[c], LIMITV);
            float l = fminf(fmaxf(lraw[w] + blp[c], -LIMITV), LIMITV);
            float s = 1.0f / (1.0f + expf(-ALPHA * g));
            hb[q*4+w] = __float2half_rn(g * s * (l + 1.0f));
        }
    }
    #pragma unroll
    for (int q = 0; q < 4; q++)
        ((float4*)outp)[q] = ((float4*)hb)[q];
}

// ---------------- GEMM2 (fp16 wmma, 3-stage pipe): y2 = act @ w2[e] ----------
#define G2_STAGE (BM*LDA + BK*LDB)     // 7424 halfs
#define G2_SMEM  (NSTG * G2_STAGE * 2) // 44544 B

__global__ __launch_bounds__(256) void gemm2_kernel() {
    int e  = blockIdx.z;
    int m0 = blockIdx.x * BM;
    int n0 = blockIdx.y * BN;
    int cnt = d_counts[e];
    if (m0 >= cnt) return;

    extern __shared__ __align__(16) __half sbuf[];

    int tid = threadIdx.x;
    const __half* Abase = d_acth + (size_t)(e * T_TOK + m0) * INTERN;
    const __half* Bbase = d_w2h + (size_t)e * INTERN * HID + n0;

    auto load_stage = [&](int s, int k0) {
        __half* as = sbuf + s * G2_STAGE;
        __half* bs = as + BM * LDA;
        #pragma unroll
        for (int j = 0; j < 2; j++) {
            int idx = tid + j * 256;
            int r = idx >> 2, c = (idx & 3) << 3;
            cpa16(as + r * LDA + c, Abase + (size_t)r * INTERN + k0 + c);
        }
        {
            int r = tid >> 3, c = (tid & 7) << 3;
            cpa16(bs + r * LDB + c, Bbase + (size_t)(k0 + r) * HID + c);
        }
        CP_COMMIT();
    };

    wmma::fragment<wmma::accumulator, 16, 16, 16, float> acc[2][2];
    #pragma unroll
    for (int i = 0; i < 2; i++)
        #pragma unroll
        for (int j = 0; j < 2; j++) wmma::fill_fragment(acc[i][j], 0.f);

    int wid = tid >> 5, wm = wid >> 1, wn = wid & 1;

    load_stage(0, 0);
    load_stage(1, BK);

    int sc = 0, sl = 2;
    for (int kt = 0; kt < KT; kt++) {
        CP_WAITG1();
        __syncthreads();
        if (kt + 2 < KT) load_stage(sl, (kt + 2) * BK);
        else CP_COMMIT();                // empty group: ledger alignment

        __half* as = sbuf + sc * G2_STAGE;
        __half* bs = as + BM * LDA;
        #pragma unroll
        for (int kk = 0; kk < BK; kk += 16) {
            wmma::fragment<wmma::matrix_a, 16, 16, 16, __half, wmma::row_major> af[2];
            wmma::fragment<wmma::matrix_b, 16, 16, 16, __half, wmma::row_major> bf[2];
            #pragma unroll
            for (int i = 0; i < 2; i++)
                wmma::load_matrix_sync(af[i], as + (wm * 32 + i * 16) * LDA + kk, LDA);
            #pragma unroll
            for (int j = 0; j < 2; j++)
                wmma::load_matrix_sync(bf[j], bs + kk * LDB + wn * 32 + j * 16, LDB);
            #pragma unroll
            for (int i = 0; i < 2; i++)
                #pragma unroll
                for (int j = 0; j < 2; j++)
                    wmma::mma_sync(acc[i][j], af[i], bf[j], acc[i][j]);
        }
        sc = (sc == NSTG - 1) ? 0 : sc + 1;
        sl = (sl == NSTG - 1) ? 0 : sl + 1;
    }

    float* Cbase = d_y2 + (size_t)(e * T_TOK + m0) * HID + n0;
    #pragma unroll
    for (int i = 0; i < 2; i++)
        #pragma unroll
        for (int j = 0; j < 2; j++)
            wmma::store_matrix_sync(Cbase + (size_t)(wm * 32 + i * 16) * HID + wn * 32 + j * 16,
                                    acc[i][j], HID, wmma::mem_row_major);
}

// ---------------- deterministic combine ----------------
__global__ void combine_kernel(const float* __restrict__ b2,
                               float* __restrict__ y) {
    int t = blockIdx.x;
    __shared__ int se[TOPK]; __shared__ int sp[TOPK]; __shared__ float sw[TOPK];
    if (threadIdx.x < TOPK) {
        se[threadIdx.x] = d_topidx[t * TOPK + threadIdx.x];
        sp[threadIdx.x] = d_pos  [t * TOPK + threadIdx.x];
        sw[threadIdx.x] = d_topw [t * TOPK + threadIdx.x];
    }
    __syncthreads();
    for (int n = threadIdx.x; n < HID; n += blockDim.x) {
        float s = 0.f;
        #pragma unroll
        for (int k = 0; k < TOPK; k++) {
            int e = se[k];
            size_t row = (size_t)(e * T_TOK + sp[k]);
            s += sw[k] * (d_y2[row * HID + n] + b2[(size_t)e * HID + n]);
        }
        y[(size_t)t * HID + n] = s;
    }
}

// ---------------- launch ----------------
extern "C" void kernel_launch(void* const* d_in, const int* in_sizes, int n_in,
                              void* d_out, int out_size) {
    const float* x  = (const float*)d_in[0];
    const float* gw = (const float*)d_in[1];
    const float* gb = (const float*)d_in[2];
    const float* w1 = (const float*)d_in[3];
    const float* b1 = (const float*)d_in[4];
    const float* w2 = (const float*)d_in[5];
    const float* b2 = (const float*)d_in[6];
    float* y = (float*)d_out;

    cudaFuncSetAttribute(gemm1_kernel, cudaFuncAttributeMaxDynamicSharedMemorySize, G1_SMEM);
    cudaFuncSetAttribute(gemm2_kernel, cudaFuncAttributeMaxDynamicSharedMemorySize, G2_SMEM);

    reset_kernel<<<1, 32>>>();
    router_kernel<<<T_TOK, 128>>>(x, gw, gb);
    build_kernel<<<(T_TOK + 255) / 256, 256>>>();

    // fp32 -> fp16 pre-pass (32B loads / 16B stores per thread)
    {
        __half* p;
        size_t n8;
        cudaGetSymbolAddress((void**)&p, d_xh);
        n8 = (size_t)T_TOK * HID / 8;
        cvt_half_kernel<<<(unsigned)((n8 + 255) / 256), 256>>>(x, p, n8);
        cudaGetSymbolAddress((void**)&p, d_w1h);
        n8 = (size_t)NE * HID * N1 / 8;
        cvt_half_kernel<<<(unsigned)((n8 + 255) / 256), 256>>>(w1, p, n8);
        cudaGetSymbolAddress((void**)&p, d_w2h);
        n8 = (size_t)NE * INTERN * HID / 8;
        cvt_half_kernel<<<(unsigned)((n8 + 255) / 256), 256>>>(w2, p, n8);
    }

    // m-tiles fastest: co-resident CTAs share B panels (L2 reuse)
    dim3 g1(T_TOK / BM, INTERN / BN, NE);   // (16, 45, 8)
    gemm1_kernel<<<g1, 256, G1_SMEM>>>(b1);

    dim3 g2(T_TOK / BM, HID / BN, NE);      // (16, 45, 8)
    gemm2_kernel<<<g2, 256, G2_SMEM>>>();

    combine_kernel<<<T_TOK, 256>>>(b2, y);
}

// round 11
// speedup vs baseline: 1.3792x; 1.0364x over previous
#include <cuda_runtime.h>
#include <cuda_fp16.h>
#include <mma.h>
#include <math.h>
#include <cstdint>

using namespace nvcuda;

#define T_TOK 2048
#define HID   2880
#define INTERN 2880
#define NE    8
#define TOPK  4
#define N1    (2*INTERN)          // 5760
#define ALPHA 1.702f
#define LIMITV 7.0f

// tiling
#define BM 128
#define BN 64
#define BK 32
#define LDA 40                    // BK + 8 halfs pad
#define LDB 72                    // BN + 8 halfs pad
#define LDBF 72                   // epilogue float staging leading dim
#define KT (HID/BK)               // 90
#define NSTG 3

// GEMM2 widened tile
#define BN2 96
#define LDB2 104                  // BN2 + 8 halfs pad (208B rows, 16B aligned)

// ---------------- scratch ----------------
__device__ int   d_counts[NE];
__device__ int   d_rtok[NE * T_TOK];
__device__ int   d_pos [T_TOK * TOPK];
__device__ int   d_topidx[T_TOK * TOPK];
__device__ float d_topw [T_TOK * TOPK];

__device__ __half d_xh [(size_t)T_TOK * HID];
__device__ __half d_w1h[(size_t)NE * HID * N1];
__device__ __half d_w2h[(size_t)NE * INTERN * HID];
__device__ __half d_acth[(size_t)NE * T_TOK * INTERN];
__device__ float  d_y2 [(size_t)NE * T_TOK * HID];

__device__ __forceinline__ void cpa16(void* smem, const void* gmem) {
    uint32_t s;
    asm("{ .reg .u64 t; cvta.to.shared.u64 t, %1; cvt.u32.u64 %0, t; }" : "=r"(s) : "l"(smem));
    asm volatile("cp.async.cg.shared.global [%0], [%1], 16;\n" :: "r"(s), "l"(gmem));
}
#define CP_COMMIT() asm volatile("cp.async.commit_group;\n")
#define CP_WAITG1() asm volatile("cp.async.wait_group 1;\n")

// ---------------- fp32 -> fp16 convert: 32B loads, 16B stores per thread ----
__global__ void cvt_half_kernel(const float* __restrict__ in,
                                __half* __restrict__ out, size_t n8) {
    size_t i = (size_t)blockIdx.x * blockDim.x + threadIdx.x;   // unit: 8 floats
    if (i >= n8) return;
    float4 a = ((const float4*)in)[2 * i];
    float4 b = ((const float4*)in)[2 * i + 1];
    union { __half2 h[4]; uint4 u4; } pk;
    pk.h[0] = __floats2half2_rn(a.x, a.y);
    pk.h[1] = __floats2half2_rn(a.z, a.w);
    pk.h[2] = __floats2half2_rn(b.x, b.y);
    pk.h[3] = __floats2half2_rn(b.z, b.w);
    ((uint4*)out)[i] = pk.u4;
}

// ---------------- router (fp32 exact) ----------------
__global__ void router_kernel(const float* __restrict__ x,
                              const float* __restrict__ gw,
                              const float* __restrict__ gb) {
    int t = blockIdx.x;
    float acc[NE];
    #pragma unroll
    for (int e = 0; e < NE; e++) acc[e] = 0.f;
    for (int h = threadIdx.x; h < HID; h += blockDim.x) {
        float xv = x[(size_t)t * HID + h];
        const float* g = gw + (size_t)h * NE;
        #pragma unroll
        for (int e = 0; e < NE; e++) acc[e] += xv * g[e];
    }
    #pragma unroll
    for (int off = 16; off > 0; off >>= 1)
        #pragma unroll
        for (int e = 0; e < NE; e++)
            acc[e] += __shfl_down_sync(0xffffffffu, acc[e], off);
    __shared__ float sred[4][NE];
    int w = threadIdx.x >> 5, lane = threadIdx.x & 31;
    if (lane == 0)
        #pragma unroll
        for (int e = 0; e < NE; e++) sred[w][e] = acc[e];
    __syncthreads();
    if (threadIdx.x == 0) {
        float lg[NE];
        #pragma unroll
        for (int e = 0; e < NE; e++)
            lg[e] = sred[0][e] + sred[1][e] + sred[2][e] + sred[3][e] + gb[e];
        int idx[TOPK]; float val[TOPK]; bool used[NE];
        #pragma unroll
        for (int e = 0; e < NE; e++) used[e] = false;
        #pragma unroll
        for (int k = 0; k < TOPK; k++) {
            int best = -1; float bv = -INFINITY;
            #pragma unroll
            for (int e = 0; e < NE; e++)
                if (!used[e] && lg[e] > bv) { bv = lg[e]; best = e; }
            used[best] = true; idx[k] = best; val[k] = bv;
        }
        float m = val[0], ex[TOPK], s = 0.f;
        #pragma unroll
        for (int k = 0; k < TOPK; k++) { ex[k] = expf(val[k] - m); s += ex[k]; }
        float inv = 1.f / s;
        #pragma unroll
        for (int k = 0; k < TOPK; k++) {
            d_topidx[t * TOPK + k] = idx[k];
            d_topw [t * TOPK + k] = ex[k] * inv;
        }
    }
}

__global__ void reset_kernel() { if (threadIdx.x < NE) d_counts[threadIdx.x] = 0; }

__global__ void build_kernel() {
    int t = blockIdx.x * blockDim.x + threadIdx.x;
    if (t >= T_TOK) return;
    #pragma unroll
    for (int k = 0; k < TOPK; k++) {
        int e = d_topidx[t * TOPK + k];
        int p = atomicAdd(&d_counts[e], 1);
        d_rtok[e * T_TOK + p] = t;
        d_pos[t * TOPK + k] = p;
    }
}

// ---------------- GEMM1 (fp16 wmma, 3-stage pipe) fused with clamped SwiGLU --
#define G1_STAGE (BM*LDA + 2*BK*LDB)   // 9728 halfs
#define G1_SMEM  (NSTG * G1_STAGE * 2) // 58368 B

__global__ __launch_bounds__(256) void gemm1_kernel(const float* __restrict__ b1) {
    int e  = blockIdx.z;
    int m0 = blockIdx.x * BM;
    int n0 = blockIdx.y * BN;
    int cnt = d_counts[e];
    if (m0 >= cnt) return;

    extern __shared__ __align__(16) __half sbuf[];
    __shared__ int stok[BM];

    int tid = threadIdx.x;
    if (tid < BM) {
        int r = m0 + tid;
        stok[tid] = (r < cnt) ? d_rtok[e * T_TOK + r] : d_rtok[e * T_TOK];
    }
    __syncthreads();

    const __half* Bg = d_w1h + (size_t)e * HID * N1 + n0;
    const __half* Bl = Bg + INTERN;

    auto load_stage = [&](int s, int k0) {
        __half* as = sbuf + s * G1_STAGE;
        __half* bg = as + BM * LDA;
        __half* bl = bg + BK * LDB;
        #pragma unroll
        for (int j = 0; j < 2; j++) {                 // A: 128 rows x 4 chunks
            int idx = tid + j * 256;
            int r = idx >> 2, c = (idx & 3) << 3;
            cpa16(as + r * LDA + c, d_xh + (size_t)stok[r] * HID + k0 + c);
        }
        {                                              // Bg, Bl: 32 rows x 8 chunks
            int r = tid >> 3, c = (tid & 7) << 3;
            const size_t g = (size_t)(k0 + r) * N1 + c;
            cpa16(bg + r * LDB + c, Bg + g);
            cpa16(bl + r * LDB + c, Bl + g);
        }
        CP_COMMIT();
    };

    wmma::fragment<wmma::accumulator, 16, 16, 16, float> ag[2][2], al[2][2];
    #pragma unroll
    for (int i = 0; i < 2; i++)
        #pragma unroll
        for (int j = 0; j < 2; j++) { wmma::fill_fragment(ag[i][j], 0.f); wmma::fill_fragment(al[i][j], 0.f); }

    int wid = tid >> 5, wm = wid >> 1, wn = wid & 1;   // 8 warps: 4m x 2n

    load_stage(0, 0);
    load_stage(1, BK);

    int sc = 0;          // slot of tile kt
    int sl = 2;          // slot for tile kt+2
    for (int kt = 0; kt < KT; kt++) {
        CP_WAITG1();                     // tile kt resident (empty groups keep ledger aligned)
        __syncthreads();                 // RAW for slot sc; WAR: all threads past compute(kt-1)
        if (kt + 2 < KT) load_stage(sl, (kt + 2) * BK);
        else CP_COMMIT();                // empty group: keeps wait_group 1 == "tile kt done"

        __half* as = sbuf + sc * G1_STAGE;
        __half* bg = as + BM * LDA;
        __half* bl = bg + BK * LDB;
        #pragma unroll
        for (int kk = 0; kk < BK; kk += 16) {
            wmma::fragment<wmma::matrix_a, 16, 16, 16, __half, wmma::row_major> af[2];
            wmma::fragment<wmma::matrix_b, 16, 16, 16, __half, wmma::row_major> bfg[2], bfl[2];
            #pragma unroll
            for (int i = 0; i < 2; i++)
                wmma::load_matrix_sync(af[i], as + (wm * 32 + i * 16) * LDA + kk, LDA);
            #pragma unroll
            for (int j = 0; j < 2; j++) {
                wmma::load_matrix_sync(bfg[j], bg + kk * LDB + wn * 32 + j * 16, LDB);
                wmma::load_matrix_sync(bfl[j], bl + kk * LDB + wn * 32 + j * 16, LDB);
            }
            #pragma unroll
            for (int i = 0; i < 2; i++)
                #pragma unroll
                for (int j = 0; j < 2; j++) {
                    wmma::mma_sync(ag[i][j], af[i], bfg[j], ag[i][j]);
                    wmma::mma_sync(al[i][j], af[i], bfl[j], al[i][j]);
                }
        }
        sc = (sc == NSTG - 1) ? 0 : sc + 1;
        sl = (sl == NSTG - 1) ? 0 : sl + 1;
    }
    __syncthreads();   // all compute done before smem reuse in epilogue

    // ---- fused epilogue: stage gate, stage lin, clamped SwiGLU, fp16 out ----
    float* stg = (float*)sbuf;   // 128*72*4 = 36864 B <= G1_SMEM
    #pragma unroll
    for (int i = 0; i < 2; i++)
        #pragma unroll
        for (int j = 0; j < 2; j++)
            wmma::store_matrix_sync(stg + (size_t)(wm * 32 + i * 16) * LDBF + wn * 32 + j * 16,
                                    ag[i][j], LDBF, wmma::mem_row_major);
    __syncthreads();

    int r  = tid >> 1;
    int cb = (tid & 1) * 32;
    float gv[32];
    #pragma unroll
    for (int q = 0; q < 8; q++) {
        float4 v = *(const float4*)(stg + r * LDBF + cb + q * 4);
        gv[q*4+0] = v.x; gv[q*4+1] = v.y; gv[q*4+2] = v.z; gv[q*4+3] = v.w;
    }
    __syncthreads();

    #pragma unroll
    for (int i = 0; i < 2; i++)
        #pragma unroll
        for (int j = 0; j < 2; j++)
            wmma::store_matrix_sync(stg + (size_t)(wm * 32 + i * 16) * LDBF + wn * 32 + j * 16,
                                    al[i][j], LDBF, wmma::mem_row_major);
    __syncthreads();

    const float* bgp = b1 + (size_t)e * N1 + n0;
    const float* blp = bgp + INTERN;
    __half* outp = d_acth + (size_t)(e * T_TOK + m0 + r) * INTERN + n0 + cb;
    __half hb[32];
    #pragma unroll
    for (int q = 0; q < 8; q++) {
        float4 lv = *(const float4*)(stg + r * LDBF + cb + q * 4);
        float lraw[4] = {lv.x, lv.y, lv.z, lv.w};
        #pragma unroll
        for (int w = 0; w < 4; w++) {
            int c = cb + q * 4 + w;
            float g = fminf(gv[q*4+w] + bgp[c], LIMITV);
            float l = fminf(fmaxf(lraw[w] + blp[c], -LIMITV), LIMITV);
            float s = 1.0f / (1.0f + expf(-ALPHA * g));
            hb[q*4+w] = __float2half_rn(g * s * (l + 1.0f));
        }
    }
    #pragma unroll
    for (int q = 0; q < 4; q++)
        ((float4*)outp)[q] = ((float4*)hb)[q];
}

// ---------------- GEMM2 (fp16 wmma, 3-stage pipe, BN2=96): y2 = act @ w2[e] --
#define G2_STAGE (BM*LDA + BK*LDB2)    // 5120 + 3328 = 8448 halfs
#define G2_SMEM  (NSTG * G2_STAGE * 2) // 50688 B

__global__ __launch_bounds__(256) void gemm2_kernel() {
    int e  = blockIdx.z;
    int m0 = blockIdx.x * BM;
    int n0 = blockIdx.y * BN2;
    int cnt = d_counts[e];
    if (m0 >= cnt) return;

    extern __shared__ __align__(16) __half sbuf[];

    int tid = threadIdx.x;
    const __half* Abase = d_acth + (size_t)(e * T_TOK + m0) * INTERN;
    const __half* Bbase = d_w2h + (size_t)e * INTERN * HID + n0;

    auto load_stage = [&](int s, int k0) {
        __half* as = sbuf + s * G2_STAGE;
        __half* bs = as + BM * LDA;
        #pragma unroll
        for (int j = 0; j < 2; j++) {                 // A: 128 rows x 4 chunks
            int idx = tid + j * 256;
            int r = idx >> 2, c = (idx & 3) << 3;
            cpa16(as + r * LDA + c, Abase + (size_t)r * INTERN + k0 + c);
        }
        // B: 32 rows x 12 chunks of 8 halfs = 384 chunks, 256 threads
        #pragma unroll
        for (int idx = tid; idx < 32 * 12; idx += 256) {
            int r = idx / 12, c = (idx % 12) * 8;
            cpa16(bs + r * LDB2 + c, Bbase + (size_t)(k0 + r) * HID + c);
        }
        CP_COMMIT();
    };

    wmma::fragment<wmma::accumulator, 16, 16, 16, float> acc[2][3];
    #pragma unroll
    for (int i = 0; i < 2; i++)
        #pragma unroll
        for (int j = 0; j < 3; j++) wmma::fill_fragment(acc[i][j], 0.f);

    int wid = tid >> 5, wm = wid >> 1, wn = wid & 1;   // 8 warps: 4m x 2n, warp tile 32x48

    load_stage(0, 0);
    load_stage(1, BK);

    int sc = 0, sl = 2;
    for (int kt = 0; kt < KT; kt++) {
        CP_WAITG1();
        __syncthreads();
        if (kt + 2 < KT) load_stage(sl, (kt + 2) * BK);
        else CP_COMMIT();                // empty group: ledger alignment

        __half* as = sbuf + sc * G2_STAGE;
        __half* bs = as + BM * LDA;
        #pragma unroll
        for (int kk = 0; kk < BK; kk += 16) {
            wmma::fragment<wmma::matrix_a, 16, 16, 16, __half, wmma::row_major> af[2];
            wmma::fragment<wmma::matrix_b, 16, 16, 16, __half, wmma::row_major> bf[3];
            #pragma unroll
            for (int i = 0; i < 2; i++)
                wmma::load_matrix_sync(af[i], as + (wm * 32 + i * 16) * LDA + kk, LDA);
            #pragma unroll
            for (int j = 0; j < 3; j++)
                wmma::load_matrix_sync(bf[j], bs + kk * LDB2 + wn * 48 + j * 16, LDB2);
            #pragma unroll
            for (int i = 0; i < 2; i++)
                #pragma unroll
                for (int j = 0; j < 3; j++)
                    wmma::mma_sync(acc[i][j], af[i], bf[j], acc[i][j]);
        }
        sc = (sc == NSTG - 1) ? 0 : sc + 1;
        sl = (sl == NSTG - 1) ? 0 : sl + 1;
    }

    float* Cbase = d_y2 + (size_t)(e * T_TOK + m0) * HID + n0;
    #pragma unroll
    for (int i = 0; i < 2; i++)
        #pragma unroll
        for (int j = 0; j < 3; j++)
            wmma::store_matrix_sync(Cbase + (size_t)(wm * 32 + i * 16) * HID + wn * 48 + j * 16,
                                    acc[i][j], HID, wmma::mem_row_major);
}

// ---------------- deterministic combine ----------------
__global__ void combine_kernel(const float* __restrict__ b2,
                               float* __restrict__ y) {
    int t = blockIdx.x;
    __shared__ int se[TOPK]; __shared__ int sp[TOPK]; __shared__ float sw[TOPK];
    if (threadIdx.x < TOPK) {
        se[threadIdx.x] = d_topidx[t * TOPK + threadIdx.x];
        sp[threadIdx.x] = d_pos  [t * TOPK + threadIdx.x];
        sw[threadIdx.x] = d_topw [t * TOPK + threadIdx.x];
    }
    __syncthreads();
    for (int n = threadIdx.x; n < HID; n += blockDim.x) {
        float s = 0.f;
        #pragma unroll
        for (int k = 0; k < TOPK; k++) {
            int e = se[k];
            size_t row = (size_t)(e * T_TOK + sp[k]);
            s += sw[k] * (d_y2[row * HID + n] + b2[(size_t)e * HID + n]);
        }
        y[(size_t)t * HID + n] = s;
    }
}

// ---------------- launch ----------------
extern "C" void kernel_launch(void* const* d_in, const int* in_sizes, int n_in,
                              void* d_out, int out_size) {
    const float* x  = (const float*)d_in[0];
    const float* gw = (const float*)d_in[1];
    const float* gb = (const float*)d_in[2];
    const float* w1 = (const float*)d_in[3];
    const float* b1 = (const float*)d_in[4];
    const float* w2 = (const float*)d_in[5];
    const float* b2 = (const float*)d_in[6];
    float* y = (float*)d_out;

    cudaFuncSetAttribute(gemm1_kernel, cudaFuncAttributeMaxDynamicSharedMemorySize, G1_SMEM);
    cudaFuncSetAttribute(gemm2_kernel, cudaFuncAttributeMaxDynamicSharedMemorySize, G2_SMEM);

    reset_kernel<<<1, 32>>>();
    router_kernel<<<T_TOK, 128>>>(x, gw, gb);
    build_kernel<<<(T_TOK + 255) / 256, 256>>>();

    // fp32 -> fp16 pre-pass (32B loads / 16B stores per thread)
    {
        __half* p;
        size_t n8;
        cudaGetSymbolAddress((void**)&p, d_xh);
        n8 = (size_t)T_TOK * HID / 8;
        cvt_half_kernel<<<(unsigned)((n8 + 255) / 256), 256>>>(x, p, n8);
        cudaGetSymbolAddress((void**)&p, d_w1h);
        n8 = (size_t)NE * HID * N1 / 8;
        cvt_half_kernel<<<(unsigned)((n8 + 255) / 256), 256>>>(w1, p, n8);
        cudaGetSymbolAddress((void**)&p, d_w2h);
        n8 = (size_t)NE * INTERN * HID / 8;
        cvt_half_kernel<<<(unsigned)((n8 + 255) / 256), 256>>>(w2, p, n8);
    }

    // m-tiles fastest: co-resident CTAs share B panels (L2 reuse)
    dim3 g1(T_TOK / BM, INTERN / BN, NE);   // (16, 45, 8)
    gemm1_kernel<<<g1, 256, G1_SMEM>>>(b1);

    dim3 g2(T_TOK / BM, HID / BN2, NE);     // (16, 30, 8)
    gemm2_kernel<<<g2, 256, G2_SMEM>>>();

    combine_kernel<<<T_TOK, 256>>>(b2, y);
}